// round 2
// baseline (speedup 1.0000x reference)
#include <cuda_runtime.h>
#include <cstdint>
#include <cstddef>

#define Bsz  64
#define Hd   512
#define Tlen 512
#define G4H  2048
#define Ed   256
#define NCTA 128
#define HB   (Hd * Bsz)        /* 32768 floats per h buffer */
#define CHF  4096              /* floats per staged chunk: 64 k-rows x 64 b */

typedef unsigned long long ull;

// ---------------- device scratch (static, allowed) ----------------
__device__ __align__(256) float g_xg[(size_t)Tlen * G4H * Bsz];  // 256 MB
__device__ __align__(256) float g_h0[2 * HB];
__device__ __align__(256) float g_h1[2 * HB];
__device__ unsigned g_cnt = 0;
__device__ unsigned g_gen = 0;

// ---------------- packed f32x2 helpers ----------------
__device__ __forceinline__ ull pk2s(float x) {
    unsigned u = __float_as_uint(x);
    ull r;
    asm("mov.b64 %0, {%1, %1};" : "=l"(r) : "r"(u));
    return r;
}
__device__ __forceinline__ void ffma2(ull& a, ull h, ull w) {
    asm("fma.rn.f32x2 %0, %1, %2, %0;" : "+l"(a) : "l"(h), "l"(w));
}
__device__ __forceinline__ void up2(ull v, float& x, float& y) {
    unsigned lo, hi;
    asm("mov.b64 {%0, %1}, %2;" : "=r"(lo), "=r"(hi) : "l"(v));
    x = __uint_as_float(lo);
    y = __uint_as_float(hi);
}

__device__ __forceinline__ float sigm(float x) { return 1.f / (1.f + __expf(-x)); }

// ---------------- cp.async chunk stage: 16KB by 256 threads ----------------
__device__ __forceinline__ void cpchunk(float* dst, const float* src) {
    unsigned d = (unsigned)__cvta_generic_to_shared(dst) + threadIdx.x * 16u;
    const char* s = (const char*)src + threadIdx.x * 16;
#pragma unroll
    for (int i = 0; i < 4; i++)
        asm volatile("cp.async.cg.shared.global [%0], [%1], 16;"
                     :: "r"(d + (unsigned)(i * 4096)), "l"(s + i * 4096));
    asm volatile("cp.async.commit_group;" ::: "memory");
}

// ---------------- grid-wide barrier (128 co-resident CTAs) ----------------
__device__ __forceinline__ void gridbar() {
    __threadfence();          // release this thread's writes
    __syncthreads();
    if (threadIdx.x == 0) {
        volatile unsigned* vg = &g_gen;
        unsigned gen = *vg;
        unsigned my = atomicAdd(&g_cnt, 1u);
        if (my == NCTA - 1u) {
            atomicExch(&g_cnt, 0u);
            __threadfence();
            atomicAdd(&g_gen, 1u);
        } else {
            while (*vg == gen) { }
        }
        __threadfence();      // acquire
    }
    __syncthreads();
}

// =================================================================
// Kernel A: Xg[t][row][b] = b0[row] + sum_e emb[x[b,t],e] * Wih0[row,e]
// grid (Tlen, 32) x 256 threads; block tile = 64 rows x 64 batch
// =================================================================
__global__ void __launch_bounds__(256) kA(const int* __restrict__ x,
                                          const float* __restrict__ emb,
                                          const float* __restrict__ Wih0,
                                          const float* __restrict__ b0) {
    __shared__ float ws[64 * 33];
    __shared__ float xs[64 * 33];
    __shared__ int   xr[64];
    const int tid = threadIdx.x;
    const int t   = blockIdx.x;
    const int rb  = blockIdx.y * 64;
    if (tid < 64) xr[tid] = x[tid * Tlen + t];
    __syncthreads();

    float acc[16];
#pragma unroll
    for (int i = 0; i < 16; i++) acc[i] = 0.f;
    const int r4 = tid >> 4;   // 0..15 -> row quad
    const int q  = tid & 15;   // 0..15 -> batch quad

    for (int ec = 0; ec < Ed; ec += 32) {
#pragma unroll
        for (int i = 0; i < 8; i++) {
            int idx = tid + i * 256;
            int a = idx >> 5, e = idx & 31;
            ws[a * 33 + e] = Wih0[(rb + a) * Ed + ec + e];
            xs[a * 33 + e] = emb[(size_t)xr[a] * Ed + ec + e];
        }
        __syncthreads();
#pragma unroll 8
        for (int e = 0; e < 32; e++) {
            float wv[4], xv[4];
#pragma unroll
            for (int j = 0; j < 4; j++) {
                wv[j] = ws[(r4 * 4 + j) * 33 + e];
                xv[j] = xs[(q  * 4 + j) * 33 + e];
            }
#pragma unroll
            for (int j = 0; j < 4; j++)
#pragma unroll
                for (int jj = 0; jj < 4; jj++)
                    acc[j * 4 + jj] = fmaf(wv[j], xv[jj], acc[j * 4 + jj]);
        }
        __syncthreads();
    }
#pragma unroll
    for (int j = 0; j < 4; j++) {
        int row = rb + r4 * 4 + j;
        float bv = b0[row];
        float4 o;
        o.x = acc[j * 4 + 0] + bv;
        o.y = acc[j * 4 + 1] + bv;
        o.z = acc[j * 4 + 2] + bv;
        o.w = acc[j * 4 + 3] + bv;
        *(float4*)(g_xg + ((size_t)t * G4H + row) * Bsz + q * 4) = o;
    }
}

// =================================================================
// zero init for h buffers (needed every launch: t=0 reads zeros)
// =================================================================
__global__ void kzero() {
    int i = blockIdx.x * 256 + threadIdx.x;   // grid 256 -> 65536 = 2*HB
    g_h0[i] = 0.f;
    g_h1[i] = 0.f;
}

// =================================================================
// Persistent recurrent kernel: 128 CTAs x 256 threads, 512 steps
// CTA owns hidden units [u0, u0+4) of both layers.
// smem: wT0[512][16] | wT1[1024][16] | hsA[4096] | hsB[4096] | gsm[16][64] | b1s
// =================================================================
#define SM_WT0 0
#define SM_WT1 8192
#define SM_HSA 24576
#define SM_HSB 28672
#define SM_GSM 32768
#define SM_B1  33792
#define SM_TOTF 33824
#define SMEMB  (SM_TOTF * 4)

__global__ void __launch_bounds__(256, 1) lstm_rec(const float* __restrict__ Whh0,
                                                   const float* __restrict__ Wih1,
                                                   const float* __restrict__ Whh1,
                                                   const float* __restrict__ b1) {
    extern __shared__ float sm[];
    float* wT0 = sm + SM_WT0;
    float* wT1 = sm + SM_WT1;
    float* hsA = sm + SM_HSA;
    float* hsB = sm + SM_HSB;
    float* gsm = sm + SM_GSM;
    float* b1s = sm + SM_B1;

    const int tid = threadIdx.x;
    const int u0  = blockIdx.x * 4;

    // ---- stage weights (once), transposed: wT[k][j], j = ui*4 + gate ----
    for (int idx = tid; idx < 512 * 16; idx += 256) {
        int j = idx >> 9, k = idx & 511;
        int row = ((j & 3) << 9) + u0 + (j >> 2);
        wT0[k * 16 + j] = Whh0[row * Hd + k];
    }
    for (int idx = tid; idx < 1024 * 16; idx += 256) {
        int j = idx >> 10, k = idx & 1023;
        int row = ((j & 3) << 9) + u0 + (j >> 2);
        wT1[k * 16 + j] = (k < 512) ? Wih1[row * Hd + k] : Whh1[row * Hd + (k - 512)];
    }
    if (tid < 16) {
        int row = ((tid & 3) << 9) + u0 + (tid >> 2);
        b1s[tid] = b1[row];
    }
    __syncthreads();

    // gemm role: one gate-row (of 16) x 4 batches
    const int r = tid >> 4;           // 0..15 = ui*4 + gate
    const int q = tid & 15;           // batch quad
    const int row_g = ((r & 3) << 9) + u0 + (r >> 2);
    // update role: one (unit, batch) pair
    const int uu = tid >> 6;          // 0..3
    const int bb = tid & 63;
    float c0 = 0.f, c1 = 0.f;

    for (int t = 0; t < Tlen; t++) {
        const int p = t & 1;

        // ================= phase 1: gates0 = Whh0 @ h0_prev + Xg =================
        {
            const float* src = g_h0 + (p ^ 1) * HB;
            cpchunk(hsA, src);
            ull a0 = 0ull, a1 = 0ull;
#pragma unroll 1
            for (int c = 0; c < 8; c++) {
                if (c < 7) {
                    cpchunk((c & 1) ? hsA : hsB, src + (c + 1) * CHF);
                    asm volatile("cp.async.wait_group 1;" ::: "memory");
                } else {
                    asm volatile("cp.async.wait_group 0;" ::: "memory");
                }
                __syncthreads();
                const ulonglong2* hp = (const ulonglong2*)((c & 1) ? hsB : hsA) + q;
                const float* wp = wT0 + (c << 6) * 16 + r;
#pragma unroll 16
                for (int kk = 0; kk < 64; kk++) {
                    ull w2 = pk2s(wp[kk * 16]);
                    ulonglong2 hv = hp[kk * 16];
                    ffma2(a0, hv.x, w2);
                    ffma2(a1, hv.y, w2);
                }
                __syncthreads();
            }
            float g0, g1, g2, g3;
            up2(a0, g0, g1);
            up2(a1, g2, g3);
            const float4 xg = *(const float4*)(g_xg + ((size_t)t * G4H + row_g) * Bsz + q * 4);
            gsm[r * 64 + q * 4 + 0] = g0 + xg.x;
            gsm[r * 64 + q * 4 + 1] = g1 + xg.y;
            gsm[r * 64 + q * 4 + 2] = g2 + xg.z;
            gsm[r * 64 + q * 4 + 3] = g3 + xg.w;
        }
        __syncthreads();
        {   // L0 cell update
            float gi = gsm[(uu * 4 + 0) * 64 + bb];
            float gf = gsm[(uu * 4 + 1) * 64 + bb];
            float gg = gsm[(uu * 4 + 2) * 64 + bb];
            float go = gsm[(uu * 4 + 3) * 64 + bb];
            c0 = sigm(gf) * c0 + sigm(gi) * tanhf(gg);
            float h0n = sigm(go) * tanhf(c0);
            g_h0[p * HB + (u0 + uu) * 64 + bb] = h0n;
        }

        gridbar();   // single grid sync per step

        // ============ phase 2: gates1 = [Wih1|Whh1] @ [h0n; h1_prev] + b1 ============
        {
            const float* s0 = g_h0 + p * HB;
            const float* s1 = g_h1 + (p ^ 1) * HB;
            cpchunk(hsA, s0);
            ull a0 = 0ull, a1 = 0ull;
#pragma unroll 1
            for (int c = 0; c < 16; c++) {
                if (c < 15) {
                    const float* nsrc = (c + 1 < 8) ? (s0 + (c + 1) * CHF)
                                                    : (s1 + (c + 1 - 8) * CHF);
                    cpchunk((c & 1) ? hsA : hsB, nsrc);
                    asm volatile("cp.async.wait_group 1;" ::: "memory");
                } else {
                    asm volatile("cp.async.wait_group 0;" ::: "memory");
                }
                __syncthreads();
                const ulonglong2* hp = (const ulonglong2*)((c & 1) ? hsB : hsA) + q;
                const float* wp = wT1 + (c << 6) * 16 + r;
#pragma unroll 16
                for (int kk = 0; kk < 64; kk++) {
                    ull w2 = pk2s(wp[kk * 16]);
                    ulonglong2 hv = hp[kk * 16];
                    ffma2(a0, hv.x, w2);
                    ffma2(a1, hv.y, w2);
                }
                __syncthreads();
            }
            float g0, g1, g2, g3;
            up2(a0, g0, g1);
            up2(a1, g2, g3);
            const float bv = b1s[r];
            gsm[r * 64 + q * 4 + 0] = g0 + bv;
            gsm[r * 64 + q * 4 + 1] = g1 + bv;
            gsm[r * 64 + q * 4 + 2] = g2 + bv;
            gsm[r * 64 + q * 4 + 3] = g3 + bv;
        }
        __syncthreads();
        {   // L1 cell update
            float gi = gsm[(uu * 4 + 0) * 64 + bb];
            float gf = gsm[(uu * 4 + 1) * 64 + bb];
            float gg = gsm[(uu * 4 + 2) * 64 + bb];
            float go = gsm[(uu * 4 + 3) * 64 + bb];
            c1 = sigm(gf) * c1 + sigm(gi) * tanhf(gg);
            float h1n = sigm(go) * tanhf(c1);
            g_h1[p * HB + (u0 + uu) * 64 + bb] = h1n;
        }
        __syncthreads();   // protect gsm reuse before next step's phase1 writes
    }
}

// =================================================================
// classifier on final top-layer hidden state (parity of t=511 is 1)
// =================================================================
__global__ void __launch_bounds__(128) kclf(const float* __restrict__ Wclf,
                                            const float* __restrict__ bclf,
                                            float* __restrict__ out) {
    const int tid = threadIdx.x;      // 128 = 2 outputs x 64 batch
    const int o = tid >> 6, b = tid & 63;
    const float* h = g_h1 + HB;       // parity 1
    float s = bclf[o];
#pragma unroll 8
    for (int k = 0; k < Hd; k++)
        s = fmaf(Wclf[o * Hd + k], h[k * 64 + b], s);
    out[b * 2 + o] = s;
}

// =================================================================
extern "C" void kernel_launch(void* const* d_in, const int* in_sizes, int n_in,
                              void* d_out, int out_size) {
    const int*   x    = (const int*)  d_in[0];
    const float* emb  = (const float*)d_in[1];
    const float* Wih0 = (const float*)d_in[2];
    const float* Whh0 = (const float*)d_in[3];
    const float* b0   = (const float*)d_in[4];
    const float* Wih1 = (const float*)d_in[5];
    const float* Whh1 = (const float*)d_in[6];
    const float* b1   = (const float*)d_in[7];
    const float* Wclf = (const float*)d_in[8];
    const float* bclf = (const float*)d_in[9];
    float* out = (float*)d_out;

    cudaFuncSetAttribute(lstm_rec, cudaFuncAttributeMaxDynamicSharedMemorySize, SMEMB);

    kzero<<<256, 256>>>();
    dim3 gA(Tlen, 32);
    kA<<<gA, 256>>>(x, emb, Wih0, b0);
    lstm_rec<<<NCTA, 256, SMEMB>>>(Whh0, Wih1, Whh1, b1);
    kclf<<<1, 128>>>(Wclf, bclf, out);
}

// round 3
// speedup vs baseline: 2.0312x; 2.0312x over previous
#include <cuda_runtime.h>
#include <cstdint>
#include <cstddef>

#define Bsz  64
#define Hd   512
#define Tlen 512
#define G4H  2048
#define Ed   256
#define NCTA 128
#define HB   (Hd * Bsz)

typedef unsigned long long ull;

// ---------------- device scratch (static, allowed) ----------------
__device__ __align__(256) float g_xg[(size_t)Tlen * G4H * Bsz];  // 256 MB
__device__ __align__(256) float g_h0[2 * HB];
__device__ __align__(256) float g_h1[2 * HB];
__device__ unsigned g_cnt = 0;
__device__ unsigned g_gen = 0;

// ---------------- packed f32x2 helpers ----------------
__device__ __forceinline__ ull pk2f(float x) {
    ull r; asm("mov.b64 %0, {%1, %1};" : "=l"(r) : "f"(x)); return r;
}
__device__ __forceinline__ ull pk2(float x, float y) {
    ull r; asm("mov.b64 %0, {%1, %2};" : "=l"(r) : "f"(x), "f"(y)); return r;
}
__device__ __forceinline__ void ffma2(ull& a, ull h, ull w) {
    asm("fma.rn.f32x2 %0, %1, %2, %0;" : "+l"(a) : "l"(h), "l"(w));
}
__device__ __forceinline__ void up2(ull v, float& x, float& y) {
    unsigned lo, hi;
    asm("mov.b64 {%0, %1}, %2;" : "=r"(lo), "=r"(hi) : "l"(v));
    x = __uint_as_float(lo); y = __uint_as_float(hi);
}
__device__ __forceinline__ float sigm(float x) { return 1.f / (1.f + __expf(-x)); }

// ---------------- grid-wide barrier (128 co-resident CTAs) ----------------
__device__ __forceinline__ void gridbar() {
    __threadfence();
    __syncthreads();
    if (threadIdx.x == 0) {
        volatile unsigned* vg = &g_gen;
        unsigned gen = *vg;
        if (atomicAdd(&g_cnt, 1u) == NCTA - 1u) {
            atomicExch(&g_cnt, 0u);
            __threadfence();
            atomicAdd(&g_gen, 1u);
        } else {
            while (*vg == gen) { }
        }
        __threadfence();
    }
    __syncthreads();
}

// =================================================================
// Kernel A: Xg[t][row][b] = b0[row] + sum_e emb[x[b,t],e] * Wih0[row,e]
// =================================================================
__global__ void __launch_bounds__(256) kA(const int* __restrict__ x,
                                          const float* __restrict__ emb,
                                          const float* __restrict__ Wih0,
                                          const float* __restrict__ b0) {
    __shared__ float ws[64 * 33];
    __shared__ float xs[64 * 33];
    __shared__ int   xr[64];
    const int tid = threadIdx.x;
    const int t   = blockIdx.x;
    const int rb  = blockIdx.y * 64;
    if (tid < 64) xr[tid] = x[tid * Tlen + t];
    __syncthreads();

    float acc[16];
#pragma unroll
    for (int i = 0; i < 16; i++) acc[i] = 0.f;
    const int r4 = tid >> 4;
    const int q  = tid & 15;

    for (int ec = 0; ec < Ed; ec += 32) {
#pragma unroll
        for (int i = 0; i < 8; i++) {
            int idx = tid + i * 256;
            int a = idx >> 5, e = idx & 31;
            ws[a * 33 + e] = Wih0[(rb + a) * Ed + ec + e];
            xs[a * 33 + e] = emb[(size_t)xr[a] * Ed + ec + e];
        }
        __syncthreads();
#pragma unroll 8
        for (int e = 0; e < 32; e++) {
            float wv[4], xv[4];
#pragma unroll
            for (int j = 0; j < 4; j++) {
                wv[j] = ws[(r4 * 4 + j) * 33 + e];
                xv[j] = xs[(q  * 4 + j) * 33 + e];
            }
#pragma unroll
            for (int j = 0; j < 4; j++)
#pragma unroll
                for (int jj = 0; jj < 4; jj++)
                    acc[j * 4 + jj] = fmaf(wv[j], xv[jj], acc[j * 4 + jj]);
        }
        __syncthreads();
    }
#pragma unroll
    for (int j = 0; j < 4; j++) {
        int row = rb + r4 * 4 + j;
        float bv = b0[row];
        float4 o;
        o.x = acc[j * 4 + 0] + bv;
        o.y = acc[j * 4 + 1] + bv;
        o.z = acc[j * 4 + 2] + bv;
        o.w = acc[j * 4 + 3] + bv;
        *(float4*)(g_xg + ((size_t)t * G4H + row) * Bsz + q * 4) = o;
    }
}

// =================================================================
__global__ void kzero() {
    int i = blockIdx.x * 256 + threadIdx.x;   // grid 256 -> 65536 = 2*HB
    g_h0[i] = 0.f;
    g_h1[i] = 0.f;
}

// =================================================================
// Persistent recurrent kernel: 128 CTAs x 256 threads.
// CTA owns 4 units (16 gate rows/layer). Warps split k 8 ways; each
// thread computes 8 rows x 4 batches over its warp's k-slice, h read
// directly from L2 via __ldcg (coalesced, no smem staging).
// smem: wT0[512][16] | wT1[1024][16] | pbuf[8][16][64]  = 128KB
// =================================================================
#define SM_WT0  0
#define SM_WT1  8192
#define SM_PBUF 24576
#define SM_TOTF 32768
#define SMEMB   (SM_TOTF * 4)

// GEMM over one warp's k-slice. acc[jj][p]: row jj (of 8), batch-pair p.
template <int NK>
__device__ __forceinline__ void gemm_slice(ull (&acc)[8][2], const float* wT, int kw0,
                                           const float* __restrict__ hsrc, int kh0,
                                           int rh, int q) {
    const float4* hp = (const float4*)hsrc + q;   // 16 float4 per k-row
    float4 hbuf[4];
#pragma unroll
    for (int j = 0; j < 4; j++) hbuf[j] = __ldcg(hp + (size_t)(kh0 + j) * 16);
#pragma unroll 4
    for (int i = 0; i < NK; i++) {
        float4 hc = hbuf[i & 3];
        if (i + 4 < NK) hbuf[i & 3] = __ldcg(hp + (size_t)(kh0 + i + 4) * 16);
        const float* wp = wT + (kw0 + i) * 16 + rh * 8;
        float4 wa = *(const float4*)wp;
        float4 wb = *(const float4*)(wp + 4);
        ull h01 = pk2(hc.x, hc.y);
        ull h23 = pk2(hc.z, hc.w);
        ull w2;
        w2 = pk2f(wa.x); ffma2(acc[0][0], h01, w2); ffma2(acc[0][1], h23, w2);
        w2 = pk2f(wa.y); ffma2(acc[1][0], h01, w2); ffma2(acc[1][1], h23, w2);
        w2 = pk2f(wa.z); ffma2(acc[2][0], h01, w2); ffma2(acc[2][1], h23, w2);
        w2 = pk2f(wa.w); ffma2(acc[3][0], h01, w2); ffma2(acc[3][1], h23, w2);
        w2 = pk2f(wb.x); ffma2(acc[4][0], h01, w2); ffma2(acc[4][1], h23, w2);
        w2 = pk2f(wb.y); ffma2(acc[5][0], h01, w2); ffma2(acc[5][1], h23, w2);
        w2 = pk2f(wb.z); ffma2(acc[6][0], h01, w2); ffma2(acc[6][1], h23, w2);
        w2 = pk2f(wb.w); ffma2(acc[7][0], h01, w2); ffma2(acc[7][1], h23, w2);
    }
}

__device__ __forceinline__ void store_partials(float* pbuf, ull (&acc)[8][2],
                                               int w, int rh, int q) {
#pragma unroll
    for (int jj = 0; jj < 8; jj++) {
        float4 v;
        up2(acc[jj][0], v.x, v.y);
        up2(acc[jj][1], v.z, v.w);
        *(float4*)&pbuf[((w * 16) + rh * 8 + jj) * 64 + q * 4] = v;
    }
}

__global__ void __launch_bounds__(256, 1) lstm_rec(const float* __restrict__ Whh0,
                                                   const float* __restrict__ Wih1,
                                                   const float* __restrict__ Whh1,
                                                   const float* __restrict__ b1) {
    extern __shared__ float sm[];
    float* wT0  = sm + SM_WT0;
    float* wT1  = sm + SM_WT1;
    float* pbuf = sm + SM_PBUF;

    const int tid = threadIdx.x;
    const int u0  = blockIdx.x * 4;

    // ---- stage weights once, transposed: wT[k][j], j = ui*4 + gate ----
    for (int idx = tid; idx < 512 * 16; idx += 256) {
        int j = idx >> 9, k = idx & 511;
        int row = ((j & 3) << 9) + u0 + (j >> 2);
        wT0[k * 16 + j] = Whh0[row * Hd + k];
    }
    for (int idx = tid; idx < 1024 * 16; idx += 256) {
        int j = idx >> 10, k = idx & 1023;
        int row = ((j & 3) << 9) + u0 + (j >> 2);
        wT1[k * 16 + j] = (k < 512) ? Wih1[row * Hd + k] : Whh1[row * Hd + (k - 512)];
    }
    __syncthreads();

    // gemm role
    const int w    = tid >> 5;        // warp 0..7 = k-slice
    const int lane = tid & 31;
    const int rh   = lane >> 4;       // 0..1 -> rows rh*8..rh*8+7
    const int q    = lane & 15;       // batch quad
    // update role
    const int uu = tid >> 6;          // unit 0..3
    const int bb = tid & 63;          // batch
    float c0 = 0.f, c1 = 0.f;
    float b1v[4];
#pragma unroll
    for (int g = 0; g < 4; g++) b1v[g] = b1[(g << 9) + u0 + uu];

    for (int t = 0; t < Tlen; t++) {
        const int p = t & 1;

        // prefetch this thread's Xg gates (used in L0 update, ~4K cyc later)
        float xgv[4];
#pragma unroll
        for (int g = 0; g < 4; g++)
            xgv[g] = __ldcs(&g_xg[((size_t)t * G4H + (g << 9) + u0 + uu) * Bsz + bb]);

        // ========== phase 1: partial gates0 = Whh0[:, kslice] @ h0_prev ==========
        {
            ull acc[8][2];
#pragma unroll
            for (int a = 0; a < 8; a++) { acc[a][0] = 0ull; acc[a][1] = 0ull; }
            gemm_slice<64>(acc, wT0, w * 64, g_h0 + (p ^ 1) * HB, w * 64, rh, q);
            store_partials(pbuf, acc, w, rh, q);
        }
        __syncthreads();
        // ---- L0 reduce + update ----
        {
            float s[4];
#pragma unroll
            for (int g = 0; g < 4; g++) {
                float v = xgv[g];
#pragma unroll
                for (int w8 = 0; w8 < 8; w8++)
                    v += pbuf[(w8 * 16 + uu * 4 + g) * 64 + bb];
                s[g] = v;
            }
            c0 = sigm(s[1]) * c0 + sigm(s[0]) * tanhf(s[2]);
            float h0n = sigm(s[3]) * tanhf(c0);
            g_h0[p * HB + (u0 + uu) * 64 + bb] = h0n;
        }

        gridbar();    // all CTAs' h0n visible; also fences pbuf reuse

        // ========== phase 2: partial gates1 = [Wih1|Whh1][:, kslice] @ [h0n; h1_prev] ==========
        {
            ull acc[8][2];
#pragma unroll
            for (int a = 0; a < 8; a++) { acc[a][0] = 0ull; acc[a][1] = 0ull; }
            if (w < 4)
                gemm_slice<128>(acc, wT1, w * 128, g_h0 + p * HB, w * 128, rh, q);
            else
                gemm_slice<128>(acc, wT1, 512 + (w - 4) * 128,
                                g_h1 + (p ^ 1) * HB, (w - 4) * 128, rh, q);
            store_partials(pbuf, acc, w, rh, q);
        }
        __syncthreads();
        // ---- L1 reduce + update ----
        {
            float s[4];
#pragma unroll
            for (int g = 0; g < 4; g++) {
                float v = b1v[g];
#pragma unroll
                for (int w8 = 0; w8 < 8; w8++)
                    v += pbuf[(w8 * 16 + uu * 4 + g) * 64 + bb];
                s[g] = v;
            }
            c1 = sigm(s[1]) * c1 + sigm(s[0]) * tanhf(s[2]);
            float h1n = sigm(s[3]) * tanhf(c1);
            g_h1[p * HB + (u0 + uu) * 64 + bb] = h1n;
        }
        __syncthreads();   // pbuf reads done before next step's stores
    }
}

// =================================================================
// classifier: 1024 threads, k split 8 ways + smem tree
// =================================================================
__global__ void __launch_bounds__(1024) kclf(const float* __restrict__ Wclf,
                                             const float* __restrict__ bclf,
                                             float* __restrict__ out) {
    __shared__ float red[1024];
    const int t  = threadIdx.x;
    const int o  = t & 1;
    const int b  = (t >> 1) & 63;
    const int ks = t >> 7;            // 0..7
    const float* h = g_h1 + HB;       // parity of t=511 is 1
    float s = 0.f;
#pragma unroll 8
    for (int i = 0; i < 64; i++) {
        int k = ks * 64 + i;
        s = fmaf(Wclf[o * Hd + k], h[k * 64 + b], s);
    }
    red[t] = s;
    __syncthreads();
    if (ks == 0) {
        float v = s + bclf[o];
#pragma unroll
        for (int w8 = 1; w8 < 8; w8++) v += red[t + w8 * 128];
        out[b * 2 + o] = v;
    }
}

// =================================================================
extern "C" void kernel_launch(void* const* d_in, const int* in_sizes, int n_in,
                              void* d_out, int out_size) {
    const int*   x    = (const int*)  d_in[0];
    const float* emb  = (const float*)d_in[1];
    const float* Wih0 = (const float*)d_in[2];
    const float* Whh0 = (const float*)d_in[3];
    const float* b0   = (const float*)d_in[4];
    const float* Wih1 = (const float*)d_in[5];
    const float* Whh1 = (const float*)d_in[6];
    const float* b1   = (const float*)d_in[7];
    const float* Wclf = (const float*)d_in[8];
    const float* bclf = (const float*)d_in[9];
    float* out = (float*)d_out;

    cudaFuncSetAttribute(lstm_rec, cudaFuncAttributeMaxDynamicSharedMemorySize, SMEMB);

    kzero<<<256, 256>>>();
    dim3 gA(Tlen, 32);
    kA<<<gA, 256>>>(x, emb, Wih0, b0);
    lstm_rec<<<NCTA, 256, SMEMB>>>(Whh0, Wih1, Whh1, b1);
    kclf<<<1, 1024>>>(Wclf, bclf, out);
}

// round 4
// speedup vs baseline: 2.3080x; 1.1363x over previous
#include <cuda_runtime.h>
#include <cstdint>
#include <cstddef>

#define Bsz  64
#define Hd   512
#define Tlen 512
#define G4H  2048
#define Ed   256
#define NCTA 128
#define NTHR 512
#define HB   (Hd * Bsz)
#define PPAD 18

typedef unsigned long long ull;

// ---------------- device scratch (static, allowed) ----------------
__device__ __align__(256) float g_xg[(size_t)Tlen * G4H * Bsz];  // 256 MB
__device__ __align__(256) float g_h0[2 * HB];
__device__ __align__(256) float g_h1[2 * HB];
__device__ unsigned g_cnt = 0;
__device__ unsigned g_gen = 0;

// ---------------- packed f32x2 helpers ----------------
__device__ __forceinline__ ull pk2f(float x) {
    ull r; asm("mov.b64 %0, {%1, %1};" : "=l"(r) : "f"(x)); return r;
}
__device__ __forceinline__ void ffma2(ull& a, ull h, ull w) {
    asm("fma.rn.f32x2 %0, %1, %2, %0;" : "+l"(a) : "l"(h), "l"(w));
}
__device__ __forceinline__ void up2(ull v, float& x, float& y) {
    unsigned lo, hi;
    asm("mov.b64 {%0, %1}, %2;" : "=r"(lo), "=r"(hi) : "l"(v));
    x = __uint_as_float(lo); y = __uint_as_float(hi);
}
__device__ __forceinline__ float sigm(float x) { return 1.f / (1.f + __expf(-x)); }

// ---------------- grid-wide barrier (128 co-resident CTAs) ----------------
__device__ __forceinline__ void gridbar() {
    __threadfence();
    __syncthreads();
    if (threadIdx.x == 0) {
        volatile unsigned* vg = &g_gen;
        unsigned gen = *vg;
        if (atomicAdd(&g_cnt, 1u) == NCTA - 1u) {
            atomicExch(&g_cnt, 0u);
            __threadfence();
            atomicAdd(&g_gen, 1u);
        } else {
            while (*vg == gen) { }
        }
        __threadfence();
    }
    __syncthreads();
}

// =================================================================
// Kernel A: Xg[t][row][b] = b0[row] + sum_e emb[x[b,t],e] * Wih0[row,e]
// f32x2 over batch pairs; block tile 64 rows x 64 batch.
// =================================================================
__global__ void __launch_bounds__(256) kA(const int* __restrict__ x,
                                          const float* __restrict__ emb,
                                          const float* __restrict__ Wih0,
                                          const float* __restrict__ b0) {
    __shared__ float ws[64 * 33];      // [row][e]
    __shared__ float xs2[32 * 66];     // [e][b] transposed, padded
    __shared__ int   xr[64];
    const int tid = threadIdx.x;
    const int t   = blockIdx.x;
    const int rb  = blockIdx.y * 64;
    if (tid < 64) xr[tid] = x[tid * Tlen + t];
    __syncthreads();

    ull accA[4], accB[4];
#pragma unroll
    for (int j = 0; j < 4; j++) { accA[j] = 0ull; accB[j] = 0ull; }
    const int r4 = tid >> 4;           // row quad
    const int q4 = (tid & 15) * 4;     // batch base

    for (int ec = 0; ec < Ed; ec += 32) {
#pragma unroll
        for (int i = 0; i < 8; i++) {
            int idx = tid + i * 256;
            int a = idx >> 5, e = idx & 31;
            ws[a * 33 + e] = Wih0[(rb + a) * Ed + ec + e];
            xs2[e * 66 + a] = emb[(size_t)xr[a] * Ed + ec + e];
        }
        __syncthreads();
#pragma unroll 8
        for (int e = 0; e < 32; e++) {
            ull x01 = *(const ull*)&xs2[e * 66 + q4];
            ull x23 = *(const ull*)&xs2[e * 66 + q4 + 2];
#pragma unroll
            for (int j = 0; j < 4; j++) {
                ull w2 = pk2f(ws[(r4 * 4 + j) * 33 + e]);
                ffma2(accA[j], x01, w2);
                ffma2(accB[j], x23, w2);
            }
        }
        __syncthreads();
    }
#pragma unroll
    for (int j = 0; j < 4; j++) {
        int row = rb + r4 * 4 + j;
        float bv = b0[row];
        float4 o;
        up2(accA[j], o.x, o.y);
        up2(accB[j], o.z, o.w);
        o.x += bv; o.y += bv; o.z += bv; o.w += bv;
        *(float4*)(g_xg + ((size_t)t * G4H + row) * Bsz + q4) = o;
    }
}

// =================================================================
__global__ void kzero() {
    int i = blockIdx.x * 256 + threadIdx.x;   // grid 256 -> 65536 = 2*HB
    g_h0[i] = 0.f;
    g_h1[i] = 0.f;
}

// =================================================================
// Persistent recurrent kernel: 128 CTAs x 512 threads (16 warps).
// CTA owns 4 units (16 gate rows/layer). 16 warps split k; each thread
// computes 8 rows (as 4 f32x2 row-pairs) x 4 batches over its slice.
// h read straight from L2 (__ldcg float4, depth-4 ring).
// smem: wT0[512][16] | wT1[1024][16] | pbuf[16][64][18]  = 168KB
// =================================================================
#define SM_WT0  0
#define SM_WT1  8192
#define SM_PBUF 24576
#define SM_TOTF (24576 + 16 * 64 * PPAD)
#define SMEMB   (SM_TOTF * 4)

template <int NK>
__device__ __forceinline__ void gemm2(ull (&acc)[4][4], const float* wT, int kw0,
                                      const float* __restrict__ hsrc, int kh0,
                                      int rh, int q) {
    const float4* hp = (const float4*)hsrc + q;   // 16 float4 per k-row
    float4 hbuf[4];
#pragma unroll
    for (int j = 0; j < 4; j++) hbuf[j] = __ldcg(hp + (size_t)(kh0 + j) * 16);
#pragma unroll 4
    for (int i = 0; i < NK; i++) {
        float4 hc = hbuf[i & 3];
        if (i + 4 < NK) hbuf[i & 3] = __ldcg(hp + (size_t)(kh0 + i + 4) * 16);
        const ulonglong2* wp = (const ulonglong2*)(wT + (kw0 + i) * 16 + rh * 8);
        ulonglong2 wa = wp[0];
        ulonglong2 wb = wp[1];
        ull h2;
        h2 = pk2f(hc.x);
        ffma2(acc[0][0], wa.x, h2); ffma2(acc[1][0], wa.y, h2);
        ffma2(acc[2][0], wb.x, h2); ffma2(acc[3][0], wb.y, h2);
        h2 = pk2f(hc.y);
        ffma2(acc[0][1], wa.x, h2); ffma2(acc[1][1], wa.y, h2);
        ffma2(acc[2][1], wb.x, h2); ffma2(acc[3][1], wb.y, h2);
        h2 = pk2f(hc.z);
        ffma2(acc[0][2], wa.x, h2); ffma2(acc[1][2], wa.y, h2);
        ffma2(acc[2][2], wb.x, h2); ffma2(acc[3][2], wb.y, h2);
        h2 = pk2f(hc.w);
        ffma2(acc[0][3], wa.x, h2); ffma2(acc[1][3], wa.y, h2);
        ffma2(acc[2][3], wb.x, h2); ffma2(acc[3][3], wb.y, h2);
    }
}

__device__ __forceinline__ void storep(float* pbuf, ull (&acc)[4][4],
                                       int w, int rh, int q) {
#pragma unroll
    for (int p = 0; p < 4; p++)
#pragma unroll
        for (int j = 0; j < 4; j++)
            *(ull*)&pbuf[(w * 64 + q * 4 + j) * PPAD + rh * 8 + 2 * p] = acc[p][j];
}

__global__ void __launch_bounds__(NTHR, 1) lstm_rec(const float* __restrict__ Whh0,
                                                    const float* __restrict__ Wih1,
                                                    const float* __restrict__ Whh1,
                                                    const float* __restrict__ b1) {
    extern __shared__ float sm[];
    float* wT0  = sm + SM_WT0;
    float* wT1  = sm + SM_WT1;
    float* pbuf = sm + SM_PBUF;

    const int tid = threadIdx.x;
    const int u0  = blockIdx.x * 4;

    // ---- stage weights once, transposed: wT[k][j], j = unit*4 + gate ----
    for (int idx = tid; idx < 512 * 16; idx += NTHR) {
        int j = idx >> 9, k = idx & 511;
        int row = ((j & 3) << 9) + u0 + (j >> 2);
        wT0[k * 16 + j] = Whh0[row * Hd + k];
    }
    for (int idx = tid; idx < 1024 * 16; idx += NTHR) {
        int j = idx >> 10, k = idx & 1023;
        int row = ((j & 3) << 9) + u0 + (j >> 2);
        wT1[k * 16 + j] = (k < 512) ? Wih1[row * Hd + k] : Whh1[row * Hd + (k - 512)];
    }
    __syncthreads();

    // gemm role
    const int w    = tid >> 5;        // warp 0..15 = k-slice
    const int lane = tid & 31;
    const int rh   = lane >> 4;       // row octet
    const int q    = lane & 15;       // batch quad
    // update role (tid < 256)
    const int uu = tid >> 6;
    const int bb = tid & 63;
    float c0 = 0.f, c1 = 0.f;
    float b1v[4] = {0.f, 0.f, 0.f, 0.f};
    if (tid < 256)
#pragma unroll
        for (int g = 0; g < 4; g++) b1v[g] = b1[(g << 9) + u0 + uu];

    for (int t = 0; t < Tlen; t++) {
        const int p = t & 1;

        float xgv[4] = {0.f, 0.f, 0.f, 0.f};
        if (tid < 256)
#pragma unroll
            for (int g = 0; g < 4; g++)
                xgv[g] = __ldcs(&g_xg[((size_t)t * G4H + (g << 9) + u0 + uu) * Bsz + bb]);

        // ========== phase 1: partial gates0 = Whh0[:, slice] @ h0_prev ==========
        {
            ull acc[4][4];
#pragma unroll
            for (int a = 0; a < 4; a++)
#pragma unroll
                for (int b = 0; b < 4; b++) acc[a][b] = 0ull;
            gemm2<32>(acc, wT0, w * 32, g_h0 + (p ^ 1) * HB, w * 32, rh, q);
            storep(pbuf, acc, w, rh, q);
        }
        __syncthreads();
        if (tid < 256) {
            float s[4] = {xgv[0], xgv[1], xgv[2], xgv[3]};
#pragma unroll
            for (int w16 = 0; w16 < 16; w16++) {
                const float* pp = &pbuf[(w16 * 64 + bb) * PPAD + uu * 4];
                float2 v0 = *(const float2*)pp;
                float2 v1 = *(const float2*)(pp + 2);
                s[0] += v0.x; s[1] += v0.y; s[2] += v1.x; s[3] += v1.y;
            }
            c0 = sigm(s[1]) * c0 + sigm(s[0]) * tanhf(s[2]);
            float h0n = sigm(s[3]) * tanhf(c0);
            g_h0[p * HB + (u0 + uu) * 64 + bb] = h0n;
        }

        gridbar();    // publish h0n to all CTAs; also fences pbuf reuse

        // ========== phase 2: partial gates1 = [Wih1|Whh1][:, slice] @ [h0n; h1_prev] ==========
        {
            ull acc[4][4];
#pragma unroll
            for (int a = 0; a < 4; a++)
#pragma unroll
                for (int b = 0; b < 4; b++) acc[a][b] = 0ull;
            if (w < 8)
                gemm2<64>(acc, wT1, w * 64, g_h0 + p * HB, w * 64, rh, q);
            else
                gemm2<64>(acc, wT1, w * 64, g_h1 + (p ^ 1) * HB, (w - 8) * 64, rh, q);
            storep(pbuf, acc, w, rh, q);
        }
        __syncthreads();
        if (tid < 256) {
            float s[4] = {b1v[0], b1v[1], b1v[2], b1v[3]};
#pragma unroll
            for (int w16 = 0; w16 < 16; w16++) {
                const float* pp = &pbuf[(w16 * 64 + bb) * PPAD + uu * 4];
                float2 v0 = *(const float2*)pp;
                float2 v1 = *(const float2*)(pp + 2);
                s[0] += v0.x; s[1] += v0.y; s[2] += v1.x; s[3] += v1.y;
            }
            c1 = sigm(s[1]) * c1 + sigm(s[0]) * tanhf(s[2]);
            float h1n = sigm(s[3]) * tanhf(c1);
            g_h1[p * HB + (u0 + uu) * 64 + bb] = h1n;
        }
        __syncthreads();   // pbuf reads done before next step's stores
    }
}

// =================================================================
// classifier: 1024 threads, k split 8 ways + smem tree
// =================================================================
__global__ void __launch_bounds__(1024) kclf(const float* __restrict__ Wclf,
                                             const float* __restrict__ bclf,
                                             float* __restrict__ out) {
    __shared__ float red[1024];
    const int t  = threadIdx.x;
    const int o  = t & 1;
    const int b  = (t >> 1) & 63;
    const int ks = t >> 7;
    const float* h = g_h1 + HB;       // parity of t=511 is 1
    float s = 0.f;
#pragma unroll 8
    for (int i = 0; i < 64; i++) {
        int k = ks * 64 + i;
        s = fmaf(Wclf[o * Hd + k], h[k * 64 + b], s);
    }
    red[t] = s;
    __syncthreads();
    if (ks == 0) {
        float v = s + bclf[o];
#pragma unroll
        for (int w8 = 1; w8 < 8; w8++) v += red[t + w8 * 128];
        out[b * 2 + o] = v;
    }
}

// =================================================================
extern "C" void kernel_launch(void* const* d_in, const int* in_sizes, int n_in,
                              void* d_out, int out_size) {
    const int*   x    = (const int*)  d_in[0];
    const float* emb  = (const float*)d_in[1];
    const float* Wih0 = (const float*)d_in[2];
    const float* Whh0 = (const float*)d_in[3];
    const float* b0   = (const float*)d_in[4];
    const float* Wih1 = (const float*)d_in[5];
    const float* Whh1 = (const float*)d_in[6];
    const float* b1   = (const float*)d_in[7];
    const float* Wclf = (const float*)d_in[8];
    const float* bclf = (const float*)d_in[9];
    float* out = (float*)d_out;

    cudaFuncSetAttribute(lstm_rec, cudaFuncAttributeMaxDynamicSharedMemorySize, SMEMB);

    kzero<<<256, 256>>>();
    dim3 gA(Tlen, 32);
    kA<<<gA, 256>>>(x, emb, Wih0, b0);
    lstm_rec<<<NCTA, NTHR, SMEMB>>>(Whh0, Wih1, Whh1, b1);
    kclf<<<1, 1024>>>(Wclf, bclf, out);
}